// round 1
// baseline (speedup 1.0000x reference)
#include <cuda_runtime.h>

// Problem dims
#define DSZ   256
#define QL    64
#define PL    128
#define BATCH 64
#define TWO_D 512
#define FOUR_D 1024
#define LDW   33280   // (Q+1)*2D

// ---------------- scratch (device globals; allocation-free) ----------------
__device__ float g_Sp[PL * BATCH * DSZ];        // H_p @ Wa^T + ba          [P,B,D]
__device__ float g_ga[QL * BATCH * DSZ];        // H_q @ Wg^T               [Q,B,D]
__device__ float g_Xp[PL * BATCH * FOUR_D];     // H_p @ Wih_p^T + biases   [P,B,4D]
__device__ float g_U [QL * BATCH * FOUR_D];     // per-q Hq @ Wih_q^T       [Q,B,4D]

// ---------------- generic NT SGEMM: C[m,n] = sum_k A[m,k]*B[n,k] (+bias) ---
#define BM 64
#define BN 128
#define BKK 16

__global__ __launch_bounds__(256) void gemm_nt(
    const float* __restrict__ A, int lda, long Az,
    const float* __restrict__ B, int ldb, long Bz,
    float* __restrict__ C, int ldc, long Cz,
    int K,
    const float* __restrict__ bias1, const float* __restrict__ bias2)
{
    __shared__ float As[BKK][BM];
    __shared__ float Bs[BKK][BN];
    const int t  = threadIdx.x;
    const int m0 = blockIdx.y * BM;
    const int n0 = blockIdx.x * BN;
    A += (long)blockIdx.z * Az + (long)m0 * lda;
    B += (long)blockIdx.z * Bz + (long)n0 * ldb;
    C += (long)blockIdx.z * Cz;

    const int arow = t >> 2, akq = t & 3;   // A tile: 64 rows x 4 float4
    const int tx = t & 31, ty = t >> 5;     // compute mapping: 8x4 per thread

    float acc[8][4];
#pragma unroll
    for (int i = 0; i < 8; i++)
#pragma unroll
        for (int j = 0; j < 4; j++) acc[i][j] = 0.f;

    for (int k0 = 0; k0 < K; k0 += BKK) {
        float4 av = *(const float4*)(A + (long)arow * lda + k0 + akq * 4);
        As[akq * 4 + 0][arow] = av.x;
        As[akq * 4 + 1][arow] = av.y;
        As[akq * 4 + 2][arow] = av.z;
        As[akq * 4 + 3][arow] = av.w;
#pragma unroll
        for (int i = 0; i < 2; i++) {
            int idx = t * 2 + i;
            int brow = idx >> 2, bkq = idx & 3;
            float4 bv = *(const float4*)(B + (long)brow * ldb + k0 + bkq * 4);
            Bs[bkq * 4 + 0][brow] = bv.x;
            Bs[bkq * 4 + 1][brow] = bv.y;
            Bs[bkq * 4 + 2][brow] = bv.z;
            Bs[bkq * 4 + 3][brow] = bv.w;
        }
        __syncthreads();
#pragma unroll
        for (int k = 0; k < BKK; k++) {
            float4 a0 = *(const float4*)&As[k][ty * 8];
            float4 a1 = *(const float4*)&As[k][ty * 8 + 4];
            float4 bb = *(const float4*)&Bs[k][tx * 4];
            float am[8] = {a0.x, a0.y, a0.z, a0.w, a1.x, a1.y, a1.z, a1.w};
            float bv[4] = {bb.x, bb.y, bb.z, bb.w};
#pragma unroll
            for (int i = 0; i < 8; i++)
#pragma unroll
                for (int j = 0; j < 4; j++) acc[i][j] += am[i] * bv[j];
        }
        __syncthreads();
    }

#pragma unroll
    for (int i = 0; i < 8; i++) {
        int m = m0 + ty * 8 + i;
#pragma unroll
        for (int j = 0; j < 4; j++) {
            int n = n0 + tx * 4 + j;
            float v = acc[i][j];
            if (bias1) v += bias1[n];
            if (bias2) v += bias2[n];
            C[(long)m * ldc + n] = v;
        }
    }
}

// ---------------- recurrent scan: one CTA per batch element ----------------
__device__ __forceinline__ float tanh_fast(float x) {
    float y;
    asm("tanh.approx.f32 %0, %1;" : "=f"(y) : "f"(x));
    return y;
}
__device__ __forceinline__ float sigmoidf_(float x) {
    return 1.f / (1.f + __expf(-x));
}
__device__ __forceinline__ float warp_sum(float v) {
#pragma unroll
    for (int o = 16; o > 0; o >>= 1) v += __shfl_xor_sync(0xffffffffu, v, o);
    return v;
}

__global__ __launch_bounds__(1024, 1) void recurrent_kernel(
    const float* __restrict__ h0, const float* __restrict__ c0,
    const float* __restrict__ Wb, const float* __restrict__ alpha_w,
    const float* __restrict__ alpha_b, const float* __restrict__ Whh,
    float* __restrict__ out)
{
    const int b = blockIdx.x;
    const int tid = threadIdx.x;
    const int lane = tid & 31, warp = tid >> 5;

    __shared__ float h_sm[DSZ], c_sm[DSZ], s_sm[DSZ];
    __shared__ float part[4][DSZ];
    __shared__ float logit_sm[QL], alpha_sm[QL], aw_sm[DSZ];
    __shared__ float gate_sm[FOUR_D];
    __shared__ float ab_sm;

    if (tid < DSZ) {
        h_sm[tid]  = h0[b * DSZ + tid];
        c_sm[tid]  = c0[b * DSZ + tid];
        aw_sm[tid] = alpha_w[tid];
    }
    if (tid == 0) ab_sm = alpha_b[0];
    __syncthreads();
    const float ab = ab_sm;

    for (int t = 0; t < PL; t++) {
        // ---- s = Sp[t,b,:] + h @ Wb^T  (4-way split over e) ----
        {
            const int d = tid & (DSZ - 1), p = tid >> 8;
            const float4* wr = (const float4*)(Wb + d * DSZ + p * 64);
            const float4* h4 = ((const float4*)h_sm) + p * 16;
            float a = 0.f;
#pragma unroll
            for (int k = 0; k < 16; k++) {
                float4 w = __ldg(&wr[k]);
                float4 hv = h4[k];
                a += w.x * hv.x + w.y * hv.y + w.z * hv.z + w.w * hv.w;
            }
            part[p][d] = a;
        }
        __syncthreads();
        if (tid < DSZ) {
            s_sm[tid] = g_Sp[((long)t * BATCH + b) * DSZ + tid] +
                        part[0][tid] + part[1][tid] + part[2][tid] + part[3][tid];
        }
        __syncthreads();

        // ---- logits[q] = sum_d tanh(ga+s)*alpha_w + alpha_b (2 q per warp) ----
#pragma unroll
        for (int qq = 0; qq < 2; qq++) {
            const int q = warp + qq * 32;
            const float* gap = g_ga + ((long)q * BATCH + b) * DSZ;
            float a = 0.f;
#pragma unroll
            for (int k = 0; k < 8; k++) {
                int dd = lane + 32 * k;
                a += tanh_fast(gap[dd] + s_sm[dd]) * aw_sm[dd];
            }
            a = warp_sum(a);
            if (lane == 0) logit_sm[q] = a + ab;
        }
        __syncthreads();

        // ---- softmax over Q=64 (warp 0) ----
        if (warp == 0) {
            float x0 = logit_sm[lane], x1 = logit_sm[lane + 32];
            float m = fmaxf(x0, x1);
#pragma unroll
            for (int o = 16; o > 0; o >>= 1) m = fmaxf(m, __shfl_xor_sync(0xffffffffu, m, o));
            float e0 = __expf(x0 - m), e1 = __expf(x1 - m);
            float s = e0 + e1;
#pragma unroll
            for (int o = 16; o > 0; o >>= 1) s += __shfl_xor_sync(0xffffffffu, s, o);
            float inv = 1.f / s;
            alpha_sm[lane] = e0 * inv;
            alpha_sm[lane + 32] = e1 * inv;
        }
        __syncthreads();

        // ---- gates = Xp[t,b,:] + h @ Whh^T + sum_q alpha[q]*U[q,b,:] ----
        {
            float a = g_Xp[((long)t * BATCH + b) * FOUR_D + tid];
            const float4* wr = (const float4*)(Whh + tid * DSZ);
            const float4* h4 = (const float4*)h_sm;
#pragma unroll 8
            for (int k = 0; k < 64; k++) {
                float4 w = __ldg(&wr[k]);
                float4 hv = h4[k];
                a += w.x * hv.x + w.y * hv.y + w.z * hv.z + w.w * hv.w;
            }
            const float* Ub = g_U + (long)b * FOUR_D + tid;
#pragma unroll 8
            for (int q = 0; q < QL; q++) {
                a += alpha_sm[q] * __ldg(&Ub[(long)q * BATCH * FOUR_D]);
            }
            gate_sm[tid] = a;
        }
        __syncthreads();

        // ---- LSTM cell update (threads 0..255), PyTorch gate order i,f,g,o ----
        if (tid < DSZ) {
            float ig = sigmoidf_(gate_sm[tid]);
            float fg = sigmoidf_(gate_sm[DSZ + tid]);
            float gg = tanhf(gate_sm[2 * DSZ + tid]);
            float og = sigmoidf_(gate_sm[3 * DSZ + tid]);
            float c = fg * c_sm[tid] + ig * gg;
            float hn = og * tanhf(c);
            c_sm[tid] = c;
            h_sm[tid] = hn;
            out[((long)t * BATCH + b) * DSZ + tid] = hn;
        }
        __syncthreads();
    }
}

// ---------------- launch ----------------
extern "C" void kernel_launch(void* const* d_in, const int* in_sizes, int n_in,
                              void* d_out, int out_size)
{
    const float* H_p     = (const float*)d_in[0];   // [P,B,2D]
    const float* h_ri    = (const float*)d_in[1];   // [1,B,D]
    const float* H_q     = (const float*)d_in[2];   // [Q,B,2D]
    const float* hidden  = (const float*)d_in[3];   // [1,B,D]
    const float* Wa      = (const float*)d_in[4];   // [D,2D]
    const float* ba      = (const float*)d_in[5];   // [D]
    const float* Wb      = (const float*)d_in[6];   // [D,D]
    const float* Wg      = (const float*)d_in[7];   // [D,2D]
    const float* alpha_w = (const float*)d_in[8];   // [D]
    const float* alpha_b = (const float*)d_in[9];   // [1]
    const float* W_ih    = (const float*)d_in[10];  // [4D, 33280]
    const float* W_hh    = (const float*)d_in[11];  // [4D, D]
    const float* b_ih    = (const float*)d_in[12];  // [4D]
    const float* b_hh    = (const float*)d_in[13];  // [4D]
    float* out = (float*)d_out;

    float *Sp, *ga, *Xp, *U;
    cudaGetSymbolAddress((void**)&Sp, g_Sp);
    cudaGetSymbolAddress((void**)&ga, g_ga);
    cudaGetSymbolAddress((void**)&Xp, g_Xp);
    cudaGetSymbolAddress((void**)&U,  g_U);

    dim3 blk(256);
    // Sp = H_p @ Wa^T + ba : M=P*B=8192, N=256, K=512
    gemm_nt<<<dim3(DSZ / BN, (PL * BATCH) / BM, 1), blk>>>(
        H_p, TWO_D, 0, Wa, TWO_D, 0, Sp, DSZ, 0, TWO_D, ba, nullptr);
    // ga = H_q @ Wg^T : M=Q*B=4096, N=256, K=512
    gemm_nt<<<dim3(DSZ / BN, (QL * BATCH) / BM, 1), blk>>>(
        H_q, TWO_D, 0, Wg, TWO_D, 0, ga, DSZ, 0, TWO_D, nullptr, nullptr);
    // Xp = H_p @ W_ih[:, :512]^T + b_ih + b_hh : M=8192, N=1024, K=512
    gemm_nt<<<dim3(FOUR_D / BN, (PL * BATCH) / BM, 1), blk>>>(
        H_p, TWO_D, 0, W_ih, LDW, 0, Xp, FOUR_D, 0, TWO_D, b_ih, b_hh);
    // U[q] = H_q[q] @ W_ih[:, 512(q+1):512(q+2)]^T : per-q batched, M=64, N=1024, K=512
    gemm_nt<<<dim3(FOUR_D / BN, 1, QL), blk>>>(
        H_q, TWO_D, (long)BATCH * TWO_D,
        W_ih + TWO_D, LDW, (long)TWO_D,
        U, FOUR_D, (long)BATCH * FOUR_D, TWO_D, nullptr, nullptr);
    // Recurrent scan: one CTA per batch element
    recurrent_kernel<<<BATCH, 1024>>>(h_ri, hidden, Wb, alpha_w, alpha_b, W_hh, out);
}

// round 2
// speedup vs baseline: 3.4942x; 3.4942x over previous
#include <cuda_runtime.h>

// Problem dims
#define DSZ   256
#define QL    64
#define PL    128
#define BATCH 64
#define TWO_D 512
#define FOUR_D 1024
#define LDW   33280   // (Q+1)*2D

// ---------------- scratch (device globals; allocation-free) ----------------
__device__ float g_Sp[PL * BATCH * DSZ];        // H_p @ Wa^T + ba          [P,B,D]
__device__ float g_ga[QL * BATCH * DSZ];        // H_q @ Wg^T               [Q,B,D]
__device__ float g_Xp[PL * BATCH * FOUR_D];     // H_p @ Wih_p^T + biases   [P,B,4D]
__device__ float g_U [QL * BATCH * FOUR_D];     // per-q Hq @ Wih_q^T       [Q,B,4D]
__device__ float g_WbT [DSZ * DSZ];             // Wb^T  [k][d]
__device__ float g_WhhT[DSZ * FOUR_D];          // Whh^T [k][n]

// ---------------- transpose: out[c*R + r] = in[r*C + c] --------------------
__global__ void transpose_k(const float* __restrict__ in, float* __restrict__ out,
                            int R, int C)
{
    __shared__ float tile[32][33];
    int r0 = blockIdx.y * 32, c0 = blockIdx.x * 32;
    int x = threadIdx.x, y = threadIdx.y;       // block (32, 8)
#pragma unroll
    for (int i = 0; i < 32; i += 8)
        tile[y + i][x] = in[(long)(r0 + y + i) * C + c0 + x];
    __syncthreads();
#pragma unroll
    for (int i = 0; i < 32; i += 8)
        out[(long)(c0 + y + i) * R + r0 + x] = tile[x][y + i];
}

// ---------------- generic NT SGEMM: C[m,n] = sum_k A[m,k]*B[n,k] (+bias) ---
#define BM 64
#define BN 128
#define BKK 16

__global__ __launch_bounds__(256) void gemm_nt(
    const float* __restrict__ A, int lda, long Az,
    const float* __restrict__ B, int ldb, long Bz,
    float* __restrict__ C, int ldc, long Cz,
    int K,
    const float* __restrict__ bias1, const float* __restrict__ bias2)
{
    __shared__ float As[BKK][BM];
    __shared__ float Bs[BKK][BN];
    const int t  = threadIdx.x;
    const int m0 = blockIdx.y * BM;
    const int n0 = blockIdx.x * BN;
    A += (long)blockIdx.z * Az + (long)m0 * lda;
    B += (long)blockIdx.z * Bz + (long)n0 * ldb;
    C += (long)blockIdx.z * Cz;

    const int arow = t >> 2, akq = t & 3;
    const int tx = t & 31, ty = t >> 5;

    float acc[8][4];
#pragma unroll
    for (int i = 0; i < 8; i++)
#pragma unroll
        for (int j = 0; j < 4; j++) acc[i][j] = 0.f;

    for (int k0 = 0; k0 < K; k0 += BKK) {
        float4 av = *(const float4*)(A + (long)arow * lda + k0 + akq * 4);
        As[akq * 4 + 0][arow] = av.x;
        As[akq * 4 + 1][arow] = av.y;
        As[akq * 4 + 2][arow] = av.z;
        As[akq * 4 + 3][arow] = av.w;
#pragma unroll
        for (int i = 0; i < 2; i++) {
            int idx = t * 2 + i;
            int brow = idx >> 2, bkq = idx & 3;
            float4 bv = *(const float4*)(B + (long)brow * ldb + k0 + bkq * 4);
            Bs[bkq * 4 + 0][brow] = bv.x;
            Bs[bkq * 4 + 1][brow] = bv.y;
            Bs[bkq * 4 + 2][brow] = bv.z;
            Bs[bkq * 4 + 3][brow] = bv.w;
        }
        __syncthreads();
#pragma unroll
        for (int k = 0; k < BKK; k++) {
            float4 a0 = *(const float4*)&As[k][ty * 8];
            float4 a1 = *(const float4*)&As[k][ty * 8 + 4];
            float4 bb = *(const float4*)&Bs[k][tx * 4];
            float am[8] = {a0.x, a0.y, a0.z, a0.w, a1.x, a1.y, a1.z, a1.w};
            float bv[4] = {bb.x, bb.y, bb.z, bb.w};
#pragma unroll
            for (int i = 0; i < 8; i++)
#pragma unroll
                for (int j = 0; j < 4; j++) acc[i][j] += am[i] * bv[j];
        }
        __syncthreads();
    }

#pragma unroll
    for (int i = 0; i < 8; i++) {
        int m = m0 + ty * 8 + i;
#pragma unroll
        for (int j = 0; j < 4; j++) {
            int n = n0 + tx * 4 + j;
            float v = acc[i][j];
            if (bias1) v += bias1[n];
            if (bias2) v += bias2[n];
            C[(long)m * ldc + n] = v;
        }
    }
}

// ---------------- recurrent scan: one CTA per batch element ----------------
__device__ __forceinline__ float tanh_fast(float x) {
    float y;
    asm("tanh.approx.f32 %0, %1;" : "=f"(y) : "f"(x));
    return y;
}
__device__ __forceinline__ float sigmoidf_(float x) {
    return 1.f / (1.f + __expf(-x));
}
__device__ __forceinline__ float warp_sum(float v) {
#pragma unroll
    for (int o = 16; o > 0; o >>= 1) v += __shfl_xor_sync(0xffffffffu, v, o);
    return v;
}

__global__ __launch_bounds__(1024, 1) void recurrent_kernel(
    const float* __restrict__ h0, const float* __restrict__ c0,
    const float* __restrict__ alpha_w, const float* __restrict__ alpha_b,
    float* __restrict__ out)
{
    const int b = blockIdx.x;
    const int tid = threadIdx.x;
    const int lane = tid & 31, warp = tid >> 5;

    __shared__ float h_sm[DSZ], c_sm[DSZ], s_sm[DSZ];
    __shared__ float part_sm[4096];             // shared by s-parts and gate-parts
    __shared__ float logit_sm[QL], alpha_sm[QL], aw_sm[DSZ];
    __shared__ float gate_sm[FOUR_D];
    __shared__ float ab_sm;

    if (tid < DSZ) {
        h_sm[tid]  = h0[b * DSZ + tid];
        c_sm[tid]  = c0[b * DSZ + tid];
        aw_sm[tid] = alpha_w[tid];
    }
    if (tid == 0) ab_sm = alpha_b[0];
    __syncthreads();
    const float ab = ab_sm;

    const float4* WbT4  = (const float4*)g_WbT;    // [k][64 float4]
    const float4* WhhT4 = (const float4*)g_WhhT;   // [k][256 float4]
    const float4* U4    = (const float4*)g_U;      // [(q*B+b)][256 float4]

    for (int t = 0; t < PL; t++) {
        // ---- s = Sp[t,b,:] + h @ Wb^T   (coalesced via WbT, 16 k-parts) ----
        {
            const int d4 = tid & 63;            // float4 group over d (256 d)
            const int p  = tid >> 6;            // 16 parts x 16 k
            float4 acc = make_float4(0.f, 0.f, 0.f, 0.f);
#pragma unroll
            for (int kk = 0; kk < 16; kk++) {
                int k = p * 16 + kk;
                float4 w = __ldg(&WbT4[k * 64 + d4]);
                float hv = h_sm[k];
                acc.x += hv * w.x; acc.y += hv * w.y;
                acc.z += hv * w.z; acc.w += hv * w.w;
            }
            ((float4*)part_sm)[p * 64 + d4] = acc;   // scalar layout part_sm[p*256+d]
        }
        __syncthreads();
        if (tid < DSZ) {
            float v = g_Sp[((long)t * BATCH + b) * DSZ + tid];
#pragma unroll
            for (int p = 0; p < 16; p++) v += part_sm[p * 256 + tid];
            s_sm[tid] = v;
        }
        __syncthreads();

        // ---- logits[q] = sum_d tanh(ga+s)*alpha_w + alpha_b (2 q per warp) ----
#pragma unroll
        for (int qq = 0; qq < 2; qq++) {
            const int q = warp + qq * 32;
            const float* gap = g_ga + ((long)q * BATCH + b) * DSZ;
            float a = 0.f;
#pragma unroll
            for (int k = 0; k < 8; k++) {
                int dd = lane + 32 * k;
                a += tanh_fast(gap[dd] + s_sm[dd]) * aw_sm[dd];
            }
            a = warp_sum(a);
            if (lane == 0) logit_sm[q] = a + ab;
        }
        __syncthreads();

        // ---- warp 0: softmax; all warps: Whh partials (independent of alpha) ----
        if (warp == 0) {
            float x0 = logit_sm[lane], x1 = logit_sm[lane + 32];
            float m = fmaxf(x0, x1);
#pragma unroll
            for (int o = 16; o > 0; o >>= 1) m = fmaxf(m, __shfl_xor_sync(0xffffffffu, m, o));
            float e0 = __expf(x0 - m), e1 = __expf(x1 - m);
            float s = e0 + e1;
#pragma unroll
            for (int o = 16; o > 0; o >>= 1) s += __shfl_xor_sync(0xffffffffu, s, o);
            float inv = 1.f / s;
            alpha_sm[lane] = e0 * inv;
            alpha_sm[lane + 32] = e1 * inv;
        }

        // gates partials: n4 = float4 group over n (1024 n), p = 4 parts x 64 k
        const int n4 = tid & 255;
        const int p  = tid >> 8;
        float4 acc = make_float4(0.f, 0.f, 0.f, 0.f);
#pragma unroll 8
        for (int kk = 0; kk < 64; kk++) {
            int k = p * 64 + kk;
            float4 w = __ldg(&WhhT4[k * 256 + n4]);
            float hv = h_sm[k];
            acc.x += hv * w.x; acc.y += hv * w.y;
            acc.z += hv * w.z; acc.w += hv * w.w;
        }
        __syncthreads();   // alpha ready; also protects part_sm reuse

        // U partials: p covers 16 q's each
#pragma unroll
        for (int qq = 0; qq < 16; qq++) {
            int q = p * 16 + qq;
            float a = alpha_sm[q];
            float4 u = __ldg(&U4[(long)(q * BATCH + b) * 256 + n4]);
            acc.x += a * u.x; acc.y += a * u.y;
            acc.z += a * u.z; acc.w += a * u.w;
        }
        ((float4*)part_sm)[p * 256 + n4] = acc;   // scalar layout part_sm[p*1024+n]
        __syncthreads();

        // ---- gates = Xp + sum of 4 partials; LSTM cell update ----
        {
            float g = g_Xp[((long)t * BATCH + b) * FOUR_D + tid];
#pragma unroll
            for (int pp = 0; pp < 4; pp++) g += part_sm[pp * 1024 + tid];
            gate_sm[tid] = g;
        }
        __syncthreads();

        if (tid < DSZ) {
            float ig = sigmoidf_(gate_sm[tid]);
            float fg = sigmoidf_(gate_sm[DSZ + tid]);
            float gg = tanhf(gate_sm[2 * DSZ + tid]);
            float og = sigmoidf_(gate_sm[3 * DSZ + tid]);
            float c = fg * c_sm[tid] + ig * gg;
            float hn = og * tanhf(c);
            c_sm[tid] = c;
            h_sm[tid] = hn;
            out[((long)t * BATCH + b) * DSZ + tid] = hn;
        }
        __syncthreads();
    }
}

// ---------------- launch ----------------
extern "C" void kernel_launch(void* const* d_in, const int* in_sizes, int n_in,
                              void* d_out, int out_size)
{
    const float* H_p     = (const float*)d_in[0];
    const float* h_ri    = (const float*)d_in[1];
    const float* H_q     = (const float*)d_in[2];
    const float* hidden  = (const float*)d_in[3];
    const float* Wa      = (const float*)d_in[4];
    const float* ba      = (const float*)d_in[5];
    const float* Wb      = (const float*)d_in[6];
    const float* Wg      = (const float*)d_in[7];
    const float* alpha_w = (const float*)d_in[8];
    const float* alpha_b = (const float*)d_in[9];
    const float* W_ih    = (const float*)d_in[10];
    const float* W_hh    = (const float*)d_in[11];
    const float* b_ih    = (const float*)d_in[12];
    const float* b_hh    = (const float*)d_in[13];
    float* out = (float*)d_out;

    float *Sp, *ga, *Xp, *U, *WbT, *WhhT;
    cudaGetSymbolAddress((void**)&Sp, g_Sp);
    cudaGetSymbolAddress((void**)&ga, g_ga);
    cudaGetSymbolAddress((void**)&Xp, g_Xp);
    cudaGetSymbolAddress((void**)&U,  g_U);
    cudaGetSymbolAddress((void**)&WbT,  g_WbT);
    cudaGetSymbolAddress((void**)&WhhT, g_WhhT);

    dim3 blk(256);
    dim3 tb(32, 8);
    // Transposes (tiny)
    transpose_k<<<dim3(DSZ / 32, DSZ / 32), tb>>>(Wb, WbT, DSZ, DSZ);
    transpose_k<<<dim3(DSZ / 32, FOUR_D / 32), tb>>>(W_hh, WhhT, FOUR_D, DSZ);
    // Sp = H_p @ Wa^T + ba
    gemm_nt<<<dim3(DSZ / BN, (PL * BATCH) / BM, 1), blk>>>(
        H_p, TWO_D, 0, Wa, TWO_D, 0, Sp, DSZ, 0, TWO_D, ba, nullptr);
    // ga = H_q @ Wg^T
    gemm_nt<<<dim3(DSZ / BN, (QL * BATCH) / BM, 1), blk>>>(
        H_q, TWO_D, 0, Wg, TWO_D, 0, ga, DSZ, 0, TWO_D, nullptr, nullptr);
    // Xp = H_p @ W_ih[:, :512]^T + b_ih + b_hh
    gemm_nt<<<dim3(FOUR_D / BN, (PL * BATCH) / BM, 1), blk>>>(
        H_p, TWO_D, 0, W_ih, LDW, 0, Xp, FOUR_D, 0, TWO_D, b_ih, b_hh);
    // U[q] = H_q[q] @ W_ih[:, 512(q+1):512(q+2)]^T
    gemm_nt<<<dim3(FOUR_D / BN, 1, QL), blk>>>(
        H_q, TWO_D, (long)BATCH * TWO_D,
        W_ih + TWO_D, LDW, (long)TWO_D,
        U, FOUR_D, (long)BATCH * FOUR_D, TWO_D, nullptr, nullptr);
    // Recurrent scan
    recurrent_kernel<<<BATCH, 1024>>>(h_ri, hidden, alpha_w, alpha_b, out);
}